// round 15
// baseline (speedup 1.0000x reference)
#include <cuda_runtime.h>
#include <cuda_fp16.h>
#include <cstdint>

#define NN 100000
#define EE 1600000
#define DIN_ 32
#define HH 64
#define GG 128
#define OUTC 10

#define AGG_BLOCKS 592
#define AGG_WPB 8
#define AGG_WARPS (AGG_BLOCKS * AGG_WPB)                 // 4736
#define AGG_NPER ((NN + AGG_WARPS - 1) / AGG_WARPS)      // 22

#define EP_BLOCKS 592
#define NTILES (EE / 16)                                  // 100000 exact

typedef unsigned long long u64;
typedef unsigned int u32;
typedef unsigned short u16;

// ---------------- scratch ----------------
__device__ float  g_h [(size_t)NN * HH];      // layer output (pre-BN "hraw")
__device__ float  g_agg[(size_t)NN * HH];
__device__ __half g_proj[(size_t)EE * 64];    // per-layer edge projection (CSR order)
__device__ __half g_eah[(size_t)EE * 16];     // edge_attr fp16, CSR order
__device__ __half g_ewh[3584];                // all layers' edge weights fp16
__device__ int    g_srcs[EE];                 // src permuted to CSR order
__device__ int    g_rowptr[NN + 1];
__device__ int    g_cur[NN];
__device__ float  g_stats[4 * 2 * HH];
__device__ float  g_bnsc[4 * HH];
__device__ float  g_bnsf[4 * HH];
__device__ float  g_pool[GG * HH];
__device__ float  g_cnt[GG];

// ---------------- f32x2 helpers ----------------
__device__ __forceinline__ u64 ffma2(u64 a, u64 b, u64 c) {
    u64 d; asm("fma.rn.f32x2 %0, %1, %2, %3;" : "=l"(d) : "l"(a), "l"(b), "l"(c)); return d;
}
__device__ __forceinline__ void unpk2(u64 v, float& lo, float& hi) {
    asm("mov.b64 {%0, %1}, %2;" : "=f"(lo), "=f"(hi) : "l"(v));
}

// streaming (evict-first) accessors
__device__ __forceinline__ u32 ldcs32(const void* p) {
    u32 v; asm volatile("ld.global.cs.b32 %0, [%1];" : "=r"(v) : "l"(p)); return v;
}
__device__ __forceinline__ u16 ldcs16(const void* p) {
    u16 v; asm volatile("ld.global.cs.u16 %0, [%1];" : "=h"(v) : "l"(p)); return v;
}
__device__ __forceinline__ void stcs128(void* p, uint4 v) {
    asm volatile("st.global.cs.v4.b32 [%0], {%1,%2,%3,%4};"
                 :: "l"(p), "r"(v.x), "r"(v.y), "r"(v.z), "r"(v.w) : "memory");
}
__device__ __forceinline__ void stcs64(void* p, float2 v) {
    asm volatile("st.global.cs.v2.f32 [%0], {%1,%2};" :: "l"(p), "f"(v.x), "f"(v.y) : "memory");
}
__device__ __forceinline__ void stcs32f(void* p, float v) {
    asm volatile("st.global.cs.f32 [%0], %1;" :: "l"(p), "f"(v) : "memory");
}

// ---------------- CSR build ----------------
__global__ void hist_kernel(const int* __restrict__ eidx) {
    int e = blockIdx.x * blockDim.x + threadIdx.x;
    if (e < EE) atomicAdd(&g_cur[eidx[EE + e]], 1);
}

// scan + weight fp16 conversion (fused)
__global__ void __launch_bounds__(1024) scan_kernel(const float* __restrict__ l0_ew,
                                                    const float* __restrict__ ew) {
    int t = threadIdx.x;
    for (int i = t; i < 3584; i += 1024)
        g_ewh[i] = __float2half((i < 512) ? l0_ew[i] : ew[i - 512]);

    int sum = 0;
    if (t < 1000) {
        const int4* p = (const int4*)(g_cur + t * 100);
#pragma unroll 5
        for (int q = 0; q < 25; q++) { int4 v = p[q]; sum += v.x + v.y + v.z + v.w; }
    }
    int lane = t & 31, wid = t >> 5;
    int inc = sum;
#pragma unroll
    for (int d = 1; d < 32; d <<= 1) {
        int n = __shfl_up_sync(0xffffffffu, inc, d);
        if (lane >= d) inc += n;
    }
    __shared__ int wsum[32];
    if (lane == 31) wsum[wid] = inc;
    __syncthreads();
    if (wid == 0) {
        int wv = wsum[lane];
        int winc = wv;
#pragma unroll
        for (int d = 1; d < 32; d <<= 1) {
            int n = __shfl_up_sync(0xffffffffu, winc, d);
            if (lane >= d) winc += n;
        }
        wsum[lane] = winc - wv;
    }
    __syncthreads();
    if (t < 1000) {
        int run = inc - sum + wsum[wid];
        const int4* p = (const int4*)(g_cur + t * 100);
#pragma unroll 5
        for (int q = 0; q < 25; q++) {
            int4 v = p[q];
            int i = t * 100 + q * 4;
            int4 r; r.x = run; run += v.x; r.y = run; run += v.y;
            r.z = run; run += v.z; r.w = run; run += v.w;
            *(int4*)(g_rowptr + i) = r;
            *(int4*)(g_cur + i) = r;
        }
    }
    if (t == 1023) g_rowptr[NN] = EE;
}

// scatter: permute src + fp16(edge_attr) into CSR order (streaming stores)
__global__ void scatter_kernel(const int* __restrict__ eidx, const float* __restrict__ ea) {
    int e = blockIdx.x * blockDim.x + threadIdx.x;
    if (e >= EE) return;
    int d = eidx[EE + e];
    int pos = atomicAdd(&g_cur[d], 1);
    g_srcs[pos] = eidx[e];
    const float4* s4 = (const float4*)(ea + (size_t)e * 16);
    float4 v0 = s4[0], v1 = s4[1], v2 = s4[2], v3 = s4[3];
    __half2 h0 = __floats2half2_rn(v0.x, v0.y), h1 = __floats2half2_rn(v0.z, v0.w);
    __half2 h2 = __floats2half2_rn(v1.x, v1.y), h3 = __floats2half2_rn(v1.z, v1.w);
    __half2 h4 = __floats2half2_rn(v2.x, v2.y), h5 = __floats2half2_rn(v2.z, v2.w);
    __half2 h6 = __floats2half2_rn(v3.x, v3.y), h7 = __floats2half2_rn(v3.z, v3.w);
    __half* dst = g_eah + (size_t)pos * 16;
    stcs128(dst,     make_uint4(*(u32*)&h0, *(u32*)&h1, *(u32*)&h2, *(u32*)&h3));
    stcs128(dst + 8, make_uint4(*(u32*)&h4, *(u32*)&h5, *(u32*)&h6, *(u32*)&h7));
}

// ---------------- edge projection via HMMA, fully streaming ----------------
template <int C>
__global__ void __launch_bounds__(256) eproj_mma_kernel(
    const __half* __restrict__ ewh, const float* __restrict__ ebv,
    __half* __restrict__ proj)
{
    constexpr int NB = C / 8;
    constexpr int RS = C + 8;
    __shared__ __align__(16) __half smt[8][16 * RS];
    int wip = threadIdx.x >> 5, lane = threadIdx.x & 31;
    int gid = lane >> 2, tig = lane & 3;

    u32 bf0[NB], bf1[NB];
    float bs0[NB], bs1[NB];
#pragma unroll
    for (int nb = 0; nb < NB; nb++) {
        int col = nb * 8 + gid;
        bf0[nb] = *(const u32*)&ewh[col * 16 + tig * 2];
        bf1[nb] = *(const u32*)&ewh[col * 16 + tig * 2 + 8];
        bs0[nb] = ebv[nb * 8 + tig * 2];
        bs1[nb] = ebv[nb * 8 + tig * 2 + 1];
    }

    __half* sm = smt[wip];
    for (int tile = blockIdx.x * 8 + wip; tile < NTILES; tile += gridDim.x * 8) {
        int e0 = tile * 16;
        const __half* ar = g_eah + (size_t)e0 * 16;
        u32 a0 = ldcs32(&ar[gid * 16 + tig * 2]);
        u32 a1 = ldcs32(&ar[(gid + 8) * 16 + tig * 2]);
        u32 a2 = ldcs32(&ar[gid * 16 + tig * 2 + 8]);
        u32 a3 = ldcs32(&ar[(gid + 8) * 16 + tig * 2 + 8]);

#pragma unroll
        for (int nb = 0; nb < NB; nb++) {
            float c0 = bs0[nb], c1 = bs1[nb], c2 = bs0[nb], c3 = bs1[nb];
            asm volatile(
                "mma.sync.aligned.m16n8k16.row.col.f32.f16.f16.f32 "
                "{%0,%1,%2,%3}, {%4,%5,%6,%7}, {%8,%9}, {%0,%1,%2,%3};"
                : "+f"(c0), "+f"(c1), "+f"(c2), "+f"(c3)
                : "r"(a0), "r"(a1), "r"(a2), "r"(a3), "r"(bf0[nb]), "r"(bf1[nb]));
            __half2 lo = __floats2half2_rn(c0, c1);
            __half2 hi = __floats2half2_rn(c2, c3);
            *(__half2*)&sm[gid * RS + nb * 8 + tig * 2] = lo;
            *(__half2*)&sm[(gid + 8) * RS + nb * 8 + tig * 2] = hi;
        }
        __syncwarp();
        if (C == 64) {
#pragma unroll
            for (int pass = 0; pass < 4; pass++) {
                int row = pass * 4 + (lane >> 3);
                int off = (lane & 7) * 8;
                uint4 v = *(uint4*)&sm[row * RS + off];
                stcs128(&proj[(size_t)(e0 + row) * 64 + off], v);
            }
        } else {
#pragma unroll
            for (int pass = 0; pass < 2; pass++) {
                int row = pass * 8 + (lane >> 2);
                int off = (lane & 3) * 8;
                uint4 v = *(uint4*)&sm[row * RS + off];
                stcs128(&proj[(size_t)(e0 + row) * 32 + off], v);
            }
        }
        __syncwarp();
    }
}

// ---------------- layer-0 aggregation (C=32): lite streaming ----------------
__global__ void __launch_bounds__(256) agg32_kernel(
    const float* __restrict__ xin, const __half* __restrict__ proj,
    float* __restrict__ agg)
{
    int wip = threadIdx.x >> 5, lane = threadIdx.x & 31;
    int w = blockIdx.x * AGG_WPB + wip;
    int nbeg = w * AGG_NPER;
    if (nbeg >= NN) return;
    int nend = nbeg + AGG_NPER; if (nend > NN) nend = NN;

    int jbeg = g_rowptr[nbeg], jend = g_rowptr[nend];
    int node = nbeg;
    int next_end = g_rowptr[node + 1];
    float self = xin[(size_t)node * 32 + lane];
    float A = 0.f;

    for (int j0 = jbeg; j0 < jend; j0 += 8) {
        int m = jend - j0; if (m > 8) m = 8;
        float xs[8]; u16 pr[8];
#pragma unroll
        for (int e = 0; e < 8; e++) {
            if (e < m) {
                int s = g_srcs[j0 + e];
                xs[e] = xin[(size_t)s * 32 + lane];
                pr[e] = ldcs16(&proj[(size_t)(j0 + e) * 32 + lane]);
            }
        }
#pragma unroll
        for (int e = 0; e < 8; e++) {
            if (e < m) {
                int j = j0 + e;
                while (j >= next_end) {               // uniform across warp
                    stcs32f(&agg[(size_t)node * 32 + lane], self + A);
                    A = 0.f;
                    node++;
                    next_end = g_rowptr[node + 1];
                    self = xin[(size_t)node * 32 + lane];
                }
                A += fmaxf(xs[e] + __half2float(*(__half*)&pr[e]), 0.f);
            }
        }
    }
    while (true) {
        stcs32f(&agg[(size_t)node * 32 + lane], self + A);
        A = 0.f;
        node++;
        if (node >= nend) break;
        self = xin[(size_t)node * 32 + lane];
    }
}

// ---------------- layers 1-3 aggregation (C=64, BN+relu folded) ----------------
__global__ void __launch_bounds__(256) agg64_kernel(
    const float* __restrict__ hraw, const __half2* __restrict__ proj2,
    const float* __restrict__ bnsc, const float* __restrict__ bnsf,
    float* __restrict__ agg)
{
    int wip = threadIdx.x >> 5, lane = threadIdx.x & 31;
    int w = blockIdx.x * AGG_WPB + wip;
    int nbeg = w * AGG_NPER;
    if (nbeg >= NN) return;
    int nend = nbeg + AGG_NPER; if (nend > NN) nend = NN;
    int c0 = lane * 2;
    float sc0 = bnsc[c0], sc1 = bnsc[c0 + 1];
    float sf0 = bnsf[c0], sf1 = bnsf[c0 + 1];

    int jbeg = g_rowptr[nbeg], jend = g_rowptr[nend];
    int node = nbeg;
    int next_end = g_rowptr[node + 1];
    float2 self = *(const float2*)(hraw + (size_t)node * 64 + c0);
    float A0 = 0.f, A1 = 0.f;

    for (int j0 = jbeg; j0 < jend; j0 += 8) {
        int m = jend - j0; if (m > 8) m = 8;
        float2 xs[8]; u32 pr[8];
#pragma unroll
        for (int e = 0; e < 8; e++) {
            if (e < m) {
                int s = g_srcs[j0 + e];
                xs[e] = *(const float2*)(hraw + (size_t)s * 64 + c0);
                pr[e] = ldcs32(&proj2[(size_t)(j0 + e) * 32 + lane]);
            }
        }
#pragma unroll
        for (int e = 0; e < 8; e++) {
            if (e < m) {
                int j = j0 + e;
                while (j >= next_end) {               // uniform across warp
                    float2 o;
                    o.x = fmaxf(fmaf(self.x, sc0, sf0), 0.f) + A0;
                    o.y = fmaxf(fmaf(self.y, sc1, sf1), 0.f) + A1;
                    stcs64(&agg[(size_t)node * 64 + c0], o);
                    A0 = A1 = 0.f;
                    node++;
                    next_end = g_rowptr[node + 1];
                    self = *(const float2*)(hraw + (size_t)node * 64 + c0);
                }
                float2 p = __half22float2(*(__half2*)&pr[e]);
                float x0 = fmaxf(fmaf(xs[e].x, sc0, sf0), 0.f);
                float x1 = fmaxf(fmaf(xs[e].y, sc1, sf1), 0.f);
                A0 += fmaxf(x0 + p.x, 0.f);
                A1 += fmaxf(x1 + p.y, 0.f);
            }
        }
    }
    while (true) {
        float2 o;
        o.x = fmaxf(fmaf(self.x, sc0, sf0), 0.f) + A0;
        o.y = fmaxf(fmaf(self.y, sc1, sf1), 0.f) + A1;
        stcs64(&agg[(size_t)node * 64 + c0], o);
        A0 = A1 = 0.f;
        node++;
        if (node >= nend) break;
        self = *(const float2*)(hraw + (size_t)node * 64 + c0);
    }
}

// ---------------- fused node MLP + BN stats ----------------
template <int K>
__global__ void __launch_bounds__(256) gemm_fused_kernel(
    const float* __restrict__ in, const float* __restrict__ w1,
    const float* __restrict__ b1, const float* __restrict__ w2,
    const float* __restrict__ b2, float* __restrict__ out,
    float* __restrict__ stats)
{
    __shared__ __align__(16) float a_s[64][K + 4];
    __shared__ __align__(16) float w_s[64][68];
    __shared__ __align__(16) float h_s[64][68];
    constexpr int K4 = K / 4;
    int t = threadIdx.x;
    int n0 = blockIdx.x * 64;
    int tx = t & 15, ty = t >> 4;

    for (int i = t; i < 64 * K4; i += 256) {
        int r = i / K4, c4 = i % K4;
        *(float4*)&w_s[r][c4 * 4] = ((const float4*)w1)[i];
        int n = n0 + r;
        float4 v = (n < NN) ? ((const float4*)in)[(size_t)n * K4 + c4] : make_float4(0.f,0.f,0.f,0.f);
        *(float4*)&a_s[r][c4 * 4] = v;
    }
    __syncthreads();

    {
        u64 acc2[4][4] = {};
#pragma unroll
        for (int k = 0; k < K; k += 4) {
            ulonglong2 a[4], b[4];
#pragma unroll
            for (int i = 0; i < 4; i++) a[i] = *(const ulonglong2*)&a_s[ty * 4 + i][k];
#pragma unroll
            for (int j = 0; j < 4; j++) b[j] = *(const ulonglong2*)&w_s[tx + j * 16][k];
#pragma unroll
            for (int i = 0; i < 4; i++)
#pragma unroll
                for (int j = 0; j < 4; j++)
                    acc2[i][j] = ffma2(a[i].x, b[j].x, ffma2(a[i].y, b[j].y, acc2[i][j]));
        }
#pragma unroll
        for (int j = 0; j < 4; j++) {
            int c = tx + j * 16;
            float bb = b1[c];
#pragma unroll
            for (int i = 0; i < 4; i++) {
                float lo, hi; unpk2(acc2[i][j], lo, hi);
                h_s[ty * 4 + i][c] = fmaxf(lo + hi + bb, 0.f);
            }
        }
    }
    __syncthreads();
    for (int i = t; i < 64 * 16; i += 256) {
        int r = i >> 4, c4 = i & 15;
        *(float4*)&w_s[r][c4 * 4] = ((const float4*)w2)[i];
    }
    __syncthreads();

    float val[4][4];
    {
        u64 acc2[4][4] = {};
#pragma unroll
        for (int k = 0; k < 64; k += 4) {
            ulonglong2 a[4], b[4];
#pragma unroll
            for (int i = 0; i < 4; i++) a[i] = *(const ulonglong2*)&h_s[ty * 4 + i][k];
#pragma unroll
            for (int j = 0; j < 4; j++) b[j] = *(const ulonglong2*)&w_s[tx + j * 16][k];
#pragma unroll
            for (int i = 0; i < 4; i++)
#pragma unroll
                for (int j = 0; j < 4; j++)
                    acc2[i][j] = ffma2(a[i].x, b[j].x, ffma2(a[i].y, b[j].y, acc2[i][j]));
        }
#pragma unroll
        for (int j = 0; j < 4; j++) {
            int c = tx + j * 16;
            float bb = b2[c];
#pragma unroll
            for (int i = 0; i < 4; i++) {
                float lo, hi; unpk2(acc2[i][j], lo, hi);
                val[i][j] = fmaxf(lo + hi + bb, 0.f);
            }
        }
    }
    __syncthreads();

    float* redS = &a_s[0][0];
    float* redQ = &h_s[0][0];
#pragma unroll
    for (int j = 0; j < 4; j++) {
        int c = tx + j * 16;
        float s = 0.f, q = 0.f;
#pragma unroll
        for (int i = 0; i < 4; i++) {
            int n = n0 + ty * 4 + i;
            if (n < NN) {
                float v = val[i][j];
                out[(size_t)n * 64 + c] = v;
                s += v; q = fmaf(v, v, q);
            }
        }
        redS[ty * 64 + c] = s;
        redQ[ty * 64 + c] = q;
    }
    __syncthreads();
    if (t < 64) {
        float S = 0.f, Q = 0.f;
#pragma unroll
        for (int r = 0; r < 16; r++) { S += redS[r * 64 + t]; Q += redQ[r * 64 + t]; }
        atomicAdd(&stats[t], S);
        atomicAdd(&stats[64 + t], Q);
    }
}

// ---------------- BN coefficients ----------------
__global__ void bn_coef_kernel(const float* __restrict__ stats,
                               const float* __restrict__ gamma, const float* __restrict__ beta,
                               float* __restrict__ sc, float* __restrict__ sf) {
    int t = threadIdx.x;
    float mu = stats[t] * (1.0f / NN);
    float var = stats[64 + t] * (1.0f / NN) - mu * mu;
    float inv = rsqrtf(var + 1e-5f);
    float g = gamma[t], b = beta[t];
    sc[t] = inv * g;
    sf[t] = b - mu * inv * g;
}

// ---------------- pool (BN of last layer folded; batch sorted) ----------------
__global__ void pool_kernel(const float* __restrict__ hraw, const int* __restrict__ batch,
                            const float* __restrict__ bnsc, const float* __restrict__ bnsf) {
    int warp = blockIdx.x * (blockDim.x >> 5) + (threadIdx.x >> 5);
    int lane = threadIdx.x & 31;
    int base = warp * 32;
    if (base >= NN) return;
    int end = min(base + 32, NN);
    int c0 = lane * 2;
    float sc0 = bnsc[c0], sc1 = bnsc[c0 + 1];
    float sf0 = bnsf[c0], sf1 = bnsf[c0 + 1];

    int curb = batch[base];
    float a0 = 0.f, a1 = 0.f, cf = 0.f;
    for (int n = base; n < end; n++) {
        int b = batch[n];
        if (b != curb) {
            atomicAdd(&g_pool[curb * 64 + c0], a0);
            atomicAdd(&g_pool[curb * 64 + c0 + 1], a1);
            if (lane == 0) atomicAdd(&g_cnt[curb], cf);
            a0 = a1 = cf = 0.f;
            curb = b;
        }
        float2 v = *(const float2*)(hraw + (size_t)n * 64 + c0);
        a0 += fmaxf(fmaf(v.x, sc0, sf0), 0.f);
        a1 += fmaxf(fmaf(v.y, sc1, sf1), 0.f);
        cf += 1.f;
    }
    atomicAdd(&g_pool[curb * 64 + c0], a0);
    atomicAdd(&g_pool[curb * 64 + c0 + 1], a1);
    if (lane == 0) atomicAdd(&g_cnt[curb], cf);
}

// ---------------- MLP head ----------------
__global__ void head_kernel(const float* __restrict__ hw1, const float* __restrict__ hb1,
                            const float* __restrict__ hw2, const float* __restrict__ hb2,
                            float* __restrict__ out) {
    int g = blockIdx.x, t = threadIdx.x;
    __shared__ float p[64];
    __shared__ float z[128];
    if (t < 64) {
        float c = g_cnt[g];
        p[t] = g_pool[g * 64 + t] / fmaxf(c, 1.0f);
    }
    __syncthreads();
    float s = hb1[t];
#pragma unroll 8
    for (int k = 0; k < 64; k++) s = fmaf(p[k], hw1[t * 64 + k], s);
    z[t] = fmaxf(s, 0.f);
    __syncthreads();
    if (t < OUTC) {
        float s2 = hb2[t];
#pragma unroll 8
        for (int k = 0; k < 128; k++) s2 = fmaf(z[k], hw2[t * 128 + k], s2);
        out[g * OUTC + t] = s2;
    }
}

// ---------------- launch ----------------
extern "C" void kernel_launch(void* const* d_in, const int* in_sizes, int n_in,
                              void* d_out, int out_size) {
    const float* x     = (const float*)d_in[0];
    const int*   eidx  = (const int*)  d_in[1];
    const float* ea    = (const float*)d_in[2];
    const int*   batch = (const int*)  d_in[3];
    const float* l0_ew = (const float*)d_in[4];
    const float* l0_eb = (const float*)d_in[5];
    const float* l0_w1 = (const float*)d_in[6];
    const float* l0_b1 = (const float*)d_in[7];
    const float* l0_w2 = (const float*)d_in[8];
    const float* l0_b2 = (const float*)d_in[9];
    const float* ew    = (const float*)d_in[10];
    const float* eb    = (const float*)d_in[11];
    const float* w1    = (const float*)d_in[12];
    const float* b1    = (const float*)d_in[13];
    const float* w2    = (const float*)d_in[14];
    const float* b2    = (const float*)d_in[15];
    const float* gam   = (const float*)d_in[16];
    const float* bet   = (const float*)d_in[17];
    const float* hw1   = (const float*)d_in[18];
    const float* hb1   = (const float*)d_in[19];
    const float* hw2   = (const float*)d_in[20];
    const float* hb2   = (const float*)d_in[21];
    float* out = (float*)d_out;

    float *hp, *aggp, *statsp, *scp, *sfp, *poolp, *cntp;
    int *curp;
    __half *projp, *ewhp;
    cudaGetSymbolAddress((void**)&hp, g_h);
    cudaGetSymbolAddress((void**)&aggp, g_agg);
    cudaGetSymbolAddress((void**)&projp, g_proj);
    cudaGetSymbolAddress((void**)&ewhp, g_ewh);
    cudaGetSymbolAddress((void**)&statsp, g_stats);
    cudaGetSymbolAddress((void**)&scp, g_bnsc);
    cudaGetSymbolAddress((void**)&sfp, g_bnsf);
    cudaGetSymbolAddress((void**)&poolp, g_pool);
    cudaGetSymbolAddress((void**)&cntp, g_cnt);
    cudaGetSymbolAddress((void**)&curp, g_cur);

    cudaMemsetAsync(curp, 0, NN * sizeof(int));
    cudaMemsetAsync(statsp, 0, 4 * 2 * HH * sizeof(float));
    cudaMemsetAsync(poolp, 0, GG * HH * sizeof(float));
    cudaMemsetAsync(cntp, 0, GG * sizeof(float));

    hist_kernel<<<(EE + 255) / 256, 256>>>(eidx);
    scan_kernel<<<1, 1024>>>(l0_ew, ew);
    scatter_kernel<<<(EE + 255) / 256, 256>>>(eidx, ea);

    // layer 0
    eproj_mma_kernel<32><<<EP_BLOCKS, 256>>>(ewhp, l0_eb, projp);
    agg32_kernel<<<AGG_BLOCKS, 256>>>(x, projp, aggp);
    gemm_fused_kernel<32><<<(NN + 63) / 64, 256>>>(aggp, l0_w1, l0_b1, l0_w2, l0_b2, hp, statsp);
    bn_coef_kernel<<<1, 64>>>(statsp, gam, bet, scp, sfp);

    // layers 1..3
    for (int i = 1; i < 4; i++) {
        eproj_mma_kernel<64><<<EP_BLOCKS, 256>>>(ewhp + 512 + (i - 1) * 1024,
                                                 eb + (i - 1) * HH, projp);
        agg64_kernel<<<AGG_BLOCKS, 256>>>(hp, (const __half2*)projp,
                                          scp + (i - 1) * HH, sfp + (i - 1) * HH, aggp);
        gemm_fused_kernel<64><<<(NN + 63) / 64, 256>>>(aggp, w1 + (i - 1) * HH * HH,
                                                       b1 + (i - 1) * HH,
                                                       w2 + (i - 1) * HH * HH,
                                                       b2 + (i - 1) * HH, hp,
                                                       statsp + i * 2 * HH);
        bn_coef_kernel<<<1, 64>>>(statsp + i * 2 * HH, gam + i * HH, bet + i * HH,
                                  scp + i * HH, sfp + i * HH);
    }

    pool_kernel<<<(NN + 255) / 256, 256>>>(hp, batch, scp + 3 * HH, sfp + 3 * HH);
    head_kernel<<<GG, 128>>>(hw1, hb1, hw2, hb2, out);
}

// round 16
// speedup vs baseline: 1.0743x; 1.0743x over previous
#include <cuda_runtime.h>
#include <cuda_fp16.h>
#include <cstdint>

#define NN 100000
#define EE 1600000
#define DIN_ 32
#define HH 64
#define GG 128
#define OUTC 10

#define AGG_BLOCKS 592
#define AGG_WPB 8
#define AGG_WARPS (AGG_BLOCKS * AGG_WPB)                 // 4736
#define AGG_NPER ((NN + AGG_WARPS - 1) / AGG_WARPS)      // 22

#define EP_BLOCKS 592
#define NTILES (EE / 16)                                  // 100000 exact

typedef unsigned long long u64;
typedef unsigned int u32;

// ---------------- scratch ----------------
__device__ float  g_h [(size_t)NN * HH];      // layer output (pre-BN "hraw")
__device__ float  g_agg[(size_t)NN * HH];
__device__ __half g_projA[(size_t)EE * 64];   // edge projection ping
__device__ __half g_projB[(size_t)EE * 64];   // edge projection pong
__device__ __half g_eah[(size_t)EE * 16];     // edge_attr fp16, CSR order
__device__ __half g_ewh[3584];                // all layers' edge weights fp16
__device__ int    g_srcs[EE];                 // src permuted to CSR order
__device__ int    g_rowptr[NN + 1];
__device__ int    g_cur[NN];
__device__ float  g_stats[4 * 2 * HH];
__device__ float  g_bnsc[4 * HH];
__device__ float  g_bnsf[4 * HH];
__device__ float  g_pool[GG * HH];
__device__ float  g_cnt[GG];

// ---------------- f32x2 helpers ----------------
__device__ __forceinline__ u64 ffma2(u64 a, u64 b, u64 c) {
    u64 d; asm("fma.rn.f32x2 %0, %1, %2, %3;" : "=l"(d) : "l"(a), "l"(b), "l"(c)); return d;
}
__device__ __forceinline__ void unpk2(u64 v, float& lo, float& hi) {
    asm("mov.b64 {%0, %1}, %2;" : "=f"(lo), "=f"(hi) : "l"(v));
}

// ---------------- CSR build ----------------
__global__ void hist_kernel(const int* __restrict__ eidx) {
    int e = blockIdx.x * blockDim.x + threadIdx.x;
    if (e < EE) atomicAdd(&g_cur[eidx[EE + e]], 1);
}

// scan + weight fp16 conversion (fused)
__global__ void __launch_bounds__(1024) scan_kernel(const float* __restrict__ l0_ew,
                                                    const float* __restrict__ ew) {
    int t = threadIdx.x;
    for (int i = t; i < 3584; i += 1024)
        g_ewh[i] = __float2half((i < 512) ? l0_ew[i] : ew[i - 512]);

    int sum = 0;
    if (t < 1000) {
        const int4* p = (const int4*)(g_cur + t * 100);
#pragma unroll 5
        for (int q = 0; q < 25; q++) { int4 v = p[q]; sum += v.x + v.y + v.z + v.w; }
    }
    int lane = t & 31, wid = t >> 5;
    int inc = sum;
#pragma unroll
    for (int d = 1; d < 32; d <<= 1) {
        int n = __shfl_up_sync(0xffffffffu, inc, d);
        if (lane >= d) inc += n;
    }
    __shared__ int wsum[32];
    if (lane == 31) wsum[wid] = inc;
    __syncthreads();
    if (wid == 0) {
        int wv = wsum[lane];
        int winc = wv;
#pragma unroll
        for (int d = 1; d < 32; d <<= 1) {
            int n = __shfl_up_sync(0xffffffffu, winc, d);
            if (lane >= d) winc += n;
        }
        wsum[lane] = winc - wv;
    }
    __syncthreads();
    if (t < 1000) {
        int run = inc - sum + wsum[wid];
        const int4* p = (const int4*)(g_cur + t * 100);
#pragma unroll 5
        for (int q = 0; q < 25; q++) {
            int4 v = p[q];
            int i = t * 100 + q * 4;
            int4 r; r.x = run; run += v.x; r.y = run; run += v.y;
            r.z = run; run += v.z; r.w = run; run += v.w;
            *(int4*)(g_rowptr + i) = r;
            *(int4*)(g_cur + i) = r;
        }
    }
    if (t == 1023) g_rowptr[NN] = EE;
}

// scatter: permute src + fp16(edge_attr) into CSR order
__global__ void scatter_kernel(const int* __restrict__ eidx, const float* __restrict__ ea) {
    int e = blockIdx.x * blockDim.x + threadIdx.x;
    if (e >= EE) return;
    int d = eidx[EE + e];
    int pos = atomicAdd(&g_cur[d], 1);
    g_srcs[pos] = eidx[e];
    const float4* s4 = (const float4*)(ea + (size_t)e * 16);
    float4 v0 = s4[0], v1 = s4[1], v2 = s4[2], v3 = s4[3];
    __half2 h0 = __floats2half2_rn(v0.x, v0.y), h1 = __floats2half2_rn(v0.z, v0.w);
    __half2 h2 = __floats2half2_rn(v1.x, v1.y), h3 = __floats2half2_rn(v1.z, v1.w);
    __half2 h4 = __floats2half2_rn(v2.x, v2.y), h5 = __floats2half2_rn(v2.z, v2.w);
    __half2 h6 = __floats2half2_rn(v3.x, v3.y), h7 = __floats2half2_rn(v3.z, v3.w);
    uint4* d4 = (uint4*)(g_eah + (size_t)pos * 16);
    d4[0] = make_uint4(*(u32*)&h0, *(u32*)&h1, *(u32*)&h2, *(u32*)&h3);
    d4[1] = make_uint4(*(u32*)&h4, *(u32*)&h5, *(u32*)&h6, *(u32*)&h7);
}

// ---------------- edge projection via HMMA, fully streaming ----------------
template <int C>
__global__ void __launch_bounds__(256) eproj_mma_kernel(
    const __half* __restrict__ ewh, const float* __restrict__ ebv,
    __half* __restrict__ proj)
{
    constexpr int NB = C / 8;
    constexpr int RS = C + 8;
    __shared__ __align__(16) __half smt[8][16 * RS];
    int wip = threadIdx.x >> 5, lane = threadIdx.x & 31;
    int gid = lane >> 2, tig = lane & 3;

    u32 bf0[NB], bf1[NB];
    float bs0[NB], bs1[NB];
#pragma unroll
    for (int nb = 0; nb < NB; nb++) {
        int col = nb * 8 + gid;
        bf0[nb] = *(const u32*)&ewh[col * 16 + tig * 2];
        bf1[nb] = *(const u32*)&ewh[col * 16 + tig * 2 + 8];
        bs0[nb] = ebv[nb * 8 + tig * 2];
        bs1[nb] = ebv[nb * 8 + tig * 2 + 1];
    }

    __half* sm = smt[wip];
    for (int tile = blockIdx.x * 8 + wip; tile < NTILES; tile += gridDim.x * 8) {
        int e0 = tile * 16;
        const __half* ar = g_eah + (size_t)e0 * 16;
        u32 a0 = *(const u32*)&ar[gid * 16 + tig * 2];
        u32 a1 = *(const u32*)&ar[(gid + 8) * 16 + tig * 2];
        u32 a2 = *(const u32*)&ar[gid * 16 + tig * 2 + 8];
        u32 a3 = *(const u32*)&ar[(gid + 8) * 16 + tig * 2 + 8];

#pragma unroll
        for (int nb = 0; nb < NB; nb++) {
            float c0 = bs0[nb], c1 = bs1[nb], c2 = bs0[nb], c3 = bs1[nb];
            asm volatile(
                "mma.sync.aligned.m16n8k16.row.col.f32.f16.f16.f32 "
                "{%0,%1,%2,%3}, {%4,%5,%6,%7}, {%8,%9}, {%0,%1,%2,%3};"
                : "+f"(c0), "+f"(c1), "+f"(c2), "+f"(c3)
                : "r"(a0), "r"(a1), "r"(a2), "r"(a3), "r"(bf0[nb]), "r"(bf1[nb]));
            __half2 lo = __floats2half2_rn(c0, c1);
            __half2 hi = __floats2half2_rn(c2, c3);
            *(__half2*)&sm[gid * RS + nb * 8 + tig * 2] = lo;
            *(__half2*)&sm[(gid + 8) * RS + nb * 8 + tig * 2] = hi;
        }
        __syncwarp();
        if (C == 64) {
#pragma unroll
            for (int pass = 0; pass < 4; pass++) {
                int row = pass * 4 + (lane >> 3);
                int off = (lane & 7) * 8;
                uint4 v = *(uint4*)&sm[row * RS + off];
                *(uint4*)&proj[(size_t)(e0 + row) * 64 + off] = v;
            }
        } else {
#pragma unroll
            for (int pass = 0; pass < 2; pass++) {
                int row = pass * 8 + (lane >> 2);
                int off = (lane & 3) * 8;
                uint4 v = *(uint4*)&sm[row * RS + off];
                *(uint4*)&proj[(size_t)(e0 + row) * 32 + off] = v;
            }
        }
        __syncwarp();
    }
}

// ---------------- layer-0 aggregation (C=32): lite streaming ----------------
__global__ void __launch_bounds__(256) agg32_kernel(
    const float* __restrict__ xin, const __half* __restrict__ proj,
    float* __restrict__ agg)
{
    int wip = threadIdx.x >> 5, lane = threadIdx.x & 31;
    int w = blockIdx.x * AGG_WPB + wip;
    int nbeg = w * AGG_NPER;
    if (nbeg >= NN) return;
    int nend = nbeg + AGG_NPER; if (nend > NN) nend = NN;

    int jbeg = g_rowptr[nbeg], jend = g_rowptr[nend];
    int node = nbeg;
    int next_end = g_rowptr[node + 1];
    float self = xin[(size_t)node * 32 + lane];
    float A = 0.f;

    for (int j0 = jbeg; j0 < jend; j0 += 8) {
        int m = jend - j0; if (m > 8) m = 8;
        float xs[8]; __half pr[8];
#pragma unroll
        for (int e = 0; e < 8; e++) {
            if (e < m) {
                int s = g_srcs[j0 + e];
                xs[e] = xin[(size_t)s * 32 + lane];
                pr[e] = proj[(size_t)(j0 + e) * 32 + lane];
            }
        }
#pragma unroll
        for (int e = 0; e < 8; e++) {
            if (e < m) {
                int j = j0 + e;
                while (j >= next_end) {               // uniform across warp
                    agg[(size_t)node * 32 + lane] = self + A;
                    A = 0.f;
                    node++;
                    next_end = g_rowptr[node + 1];
                    self = xin[(size_t)node * 32 + lane];
                }
                A += fmaxf(xs[e] + __half2float(pr[e]), 0.f);
            }
        }
    }
    while (true) {
        agg[(size_t)node * 32 + lane] = self + A;
        A = 0.f;
        node++;
        if (node >= nend) break;
        self = xin[(size_t)node * 32 + lane];
    }
}

// ---------------- layers 1-3 aggregation (C=64, BN+relu folded) ----------------
__global__ void __launch_bounds__(256) agg64_kernel(
    const float* __restrict__ hraw, const __half2* __restrict__ proj2,
    const float* __restrict__ bnsc, const float* __restrict__ bnsf,
    float* __restrict__ agg)
{
    int wip = threadIdx.x >> 5, lane = threadIdx.x & 31;
    int w = blockIdx.x * AGG_WPB + wip;
    int nbeg = w * AGG_NPER;
    if (nbeg >= NN) return;
    int nend = nbeg + AGG_NPER; if (nend > NN) nend = NN;
    int c0 = lane * 2;
    float sc0 = bnsc[c0], sc1 = bnsc[c0 + 1];
    float sf0 = bnsf[c0], sf1 = bnsf[c0 + 1];

    int jbeg = g_rowptr[nbeg], jend = g_rowptr[nend];
    int node = nbeg;
    int next_end = g_rowptr[node + 1];
    float2 self = *(const float2*)(hraw + (size_t)node * 64 + c0);
    float A0 = 0.f, A1 = 0.f;

    for (int j0 = jbeg; j0 < jend; j0 += 8) {
        int m = jend - j0; if (m > 8) m = 8;
        float2 xs[8]; __half2 pr[8];
#pragma unroll
        for (int e = 0; e < 8; e++) {
            if (e < m) {
                int s = g_srcs[j0 + e];
                xs[e] = *(const float2*)(hraw + (size_t)s * 64 + c0);
                pr[e] = proj2[(size_t)(j0 + e) * 32 + lane];
            }
        }
#pragma unroll
        for (int e = 0; e < 8; e++) {
            if (e < m) {
                int j = j0 + e;
                while (j >= next_end) {               // uniform across warp
                    float2 o;
                    o.x = fmaxf(fmaf(self.x, sc0, sf0), 0.f) + A0;
                    o.y = fmaxf(fmaf(self.y, sc1, sf1), 0.f) + A1;
                    *(float2*)(agg + (size_t)node * 64 + c0) = o;
                    A0 = A1 = 0.f;
                    node++;
                    next_end = g_rowptr[node + 1];
                    self = *(const float2*)(hraw + (size_t)node * 64 + c0);
                }
                float2 p = __half22float2(pr[e]);
                float x0 = fmaxf(fmaf(xs[e].x, sc0, sf0), 0.f);
                float x1 = fmaxf(fmaf(xs[e].y, sc1, sf1), 0.f);
                A0 += fmaxf(x0 + p.x, 0.f);
                A1 += fmaxf(x1 + p.y, 0.f);
            }
        }
    }
    while (true) {
        float2 o;
        o.x = fmaxf(fmaf(self.x, sc0, sf0), 0.f) + A0;
        o.y = fmaxf(fmaf(self.y, sc1, sf1), 0.f) + A1;
        *(float2*)(agg + (size_t)node * 64 + c0) = o;
        A0 = A1 = 0.f;
        node++;
        if (node >= nend) break;
        self = *(const float2*)(hraw + (size_t)node * 64 + c0);
    }
}

// ---------------- fused node MLP + BN stats ----------------
template <int K>
__global__ void __launch_bounds__(256) gemm_fused_kernel(
    const float* __restrict__ in, const float* __restrict__ w1,
    const float* __restrict__ b1, const float* __restrict__ w2,
    const float* __restrict__ b2, float* __restrict__ out,
    float* __restrict__ stats)
{
    __shared__ __align__(16) float a_s[64][K + 4];
    __shared__ __align__(16) float w_s[64][68];
    __shared__ __align__(16) float h_s[64][68];
    constexpr int K4 = K / 4;
    int t = threadIdx.x;
    int n0 = blockIdx.x * 64;
    int tx = t & 15, ty = t >> 4;

    for (int i = t; i < 64 * K4; i += 256) {
        int r = i / K4, c4 = i % K4;
        *(float4*)&w_s[r][c4 * 4] = ((const float4*)w1)[i];
        int n = n0 + r;
        float4 v = (n < NN) ? ((const float4*)in)[(size_t)n * K4 + c4] : make_float4(0.f,0.f,0.f,0.f);
        *(float4*)&a_s[r][c4 * 4] = v;
    }
    __syncthreads();

    {
        u64 acc2[4][4] = {};
#pragma unroll
        for (int k = 0; k < K; k += 4) {
            ulonglong2 a[4], b[4];
#pragma unroll
            for (int i = 0; i < 4; i++) a[i] = *(const ulonglong2*)&a_s[ty * 4 + i][k];
#pragma unroll
            for (int j = 0; j < 4; j++) b[j] = *(const ulonglong2*)&w_s[tx + j * 16][k];
#pragma unroll
            for (int i = 0; i < 4; i++)
#pragma unroll
                for (int j = 0; j < 4; j++)
                    acc2[i][j] = ffma2(a[i].x, b[j].x, ffma2(a[i].y, b[j].y, acc2[i][j]));
        }
#pragma unroll
        for (int j = 0; j < 4; j++) {
            int c = tx + j * 16;
            float bb = b1[c];
#pragma unroll
            for (int i = 0; i < 4; i++) {
                float lo, hi; unpk2(acc2[i][j], lo, hi);
                h_s[ty * 4 + i][c] = fmaxf(lo + hi + bb, 0.f);
            }
        }
    }
    __syncthreads();
    for (int i = t; i < 64 * 16; i += 256) {
        int r = i >> 4, c4 = i & 15;
        *(float4*)&w_s[r][c4 * 4] = ((const float4*)w2)[i];
    }
    __syncthreads();

    float val[4][4];
    {
        u64 acc2[4][4] = {};
#pragma unroll
        for (int k = 0; k < 64; k += 4) {
            ulonglong2 a[4], b[4];
#pragma unroll
            for (int i = 0; i < 4; i++) a[i] = *(const ulonglong2*)&h_s[ty * 4 + i][k];
#pragma unroll
            for (int j = 0; j < 4; j++) b[j] = *(const ulonglong2*)&w_s[tx + j * 16][k];
#pragma unroll
            for (int i = 0; i < 4; i++)
#pragma unroll
                for (int j = 0; j < 4; j++)
                    acc2[i][j] = ffma2(a[i].x, b[j].x, ffma2(a[i].y, b[j].y, acc2[i][j]));
        }
#pragma unroll
        for (int j = 0; j < 4; j++) {
            int c = tx + j * 16;
            float bb = b2[c];
#pragma unroll
            for (int i = 0; i < 4; i++) {
                float lo, hi; unpk2(acc2[i][j], lo, hi);
                val[i][j] = fmaxf(lo + hi + bb, 0.f);
            }
        }
    }
    __syncthreads();

    float* redS = &a_s[0][0];
    float* redQ = &h_s[0][0];
#pragma unroll
    for (int j = 0; j < 4; j++) {
        int c = tx + j * 16;
        float s = 0.f, q = 0.f;
#pragma unroll
        for (int i = 0; i < 4; i++) {
            int n = n0 + ty * 4 + i;
            if (n < NN) {
                float v = val[i][j];
                out[(size_t)n * 64 + c] = v;
                s += v; q = fmaf(v, v, q);
            }
        }
        redS[ty * 64 + c] = s;
        redQ[ty * 64 + c] = q;
    }
    __syncthreads();
    if (t < 64) {
        float S = 0.f, Q = 0.f;
#pragma unroll
        for (int r = 0; r < 16; r++) { S += redS[r * 64 + t]; Q += redQ[r * 64 + t]; }
        atomicAdd(&stats[t], S);
        atomicAdd(&stats[64 + t], Q);
    }
}

// ---------------- BN coefficients ----------------
__global__ void bn_coef_kernel(const float* __restrict__ stats,
                               const float* __restrict__ gamma, const float* __restrict__ beta,
                               float* __restrict__ sc, float* __restrict__ sf) {
    int t = threadIdx.x;
    float mu = stats[t] * (1.0f / NN);
    float var = stats[64 + t] * (1.0f / NN) - mu * mu;
    float inv = rsqrtf(var + 1e-5f);
    float g = gamma[t], b = beta[t];
    sc[t] = inv * g;
    sf[t] = b - mu * inv * g;
}

// ---------------- pool (BN of last layer folded; batch sorted) ----------------
__global__ void pool_kernel(const float* __restrict__ hraw, const int* __restrict__ batch,
                            const float* __restrict__ bnsc, const float* __restrict__ bnsf) {
    int warp = blockIdx.x * (blockDim.x >> 5) + (threadIdx.x >> 5);
    int lane = threadIdx.x & 31;
    int base = warp * 32;
    if (base >= NN) return;
    int end = min(base + 32, NN);
    int c0 = lane * 2;
    float sc0 = bnsc[c0], sc1 = bnsc[c0 + 1];
    float sf0 = bnsf[c0], sf1 = bnsf[c0 + 1];

    int curb = batch[base];
    float a0 = 0.f, a1 = 0.f, cf = 0.f;
    for (int n = base; n < end; n++) {
        int b = batch[n];
        if (b != curb) {
            atomicAdd(&g_pool[curb * 64 + c0], a0);
            atomicAdd(&g_pool[curb * 64 + c0 + 1], a1);
            if (lane == 0) atomicAdd(&g_cnt[curb], cf);
            a0 = a1 = cf = 0.f;
            curb = b;
        }
        float2 v = *(const float2*)(hraw + (size_t)n * 64 + c0);
        a0 += fmaxf(fmaf(v.x, sc0, sf0), 0.f);
        a1 += fmaxf(fmaf(v.y, sc1, sf1), 0.f);
        cf += 1.f;
    }
    atomicAdd(&g_pool[curb * 64 + c0], a0);
    atomicAdd(&g_pool[curb * 64 + c0 + 1], a1);
    if (lane == 0) atomicAdd(&g_cnt[curb], cf);
}

// ---------------- MLP head ----------------
__global__ void head_kernel(const float* __restrict__ hw1, const float* __restrict__ hb1,
                            const float* __restrict__ hw2, const float* __restrict__ hb2,
                            float* __restrict__ out) {
    int g = blockIdx.x, t = threadIdx.x;
    __shared__ float p[64];
    __shared__ float z[128];
    if (t < 64) {
        float c = g_cnt[g];
        p[t] = g_pool[g * 64 + t] / fmaxf(c, 1.0f);
    }
    __syncthreads();
    float s = hb1[t];
#pragma unroll 8
    for (int k = 0; k < 64; k++) s = fmaf(p[k], hw1[t * 64 + k], s);
    z[t] = fmaxf(s, 0.f);
    __syncthreads();
    if (t < OUTC) {
        float s2 = hb2[t];
#pragma unroll 8
        for (int k = 0; k < 128; k++) s2 = fmaf(z[k], hw2[t * 128 + k], s2);
        out[g * OUTC + t] = s2;
    }
}

// ---------------- launch ----------------
extern "C" void kernel_launch(void* const* d_in, const int* in_sizes, int n_in,
                              void* d_out, int out_size) {
    const float* x     = (const float*)d_in[0];
    const int*   eidx  = (const int*)  d_in[1];
    const float* ea    = (const float*)d_in[2];
    const int*   batch = (const int*)  d_in[3];
    const float* l0_ew = (const float*)d_in[4];
    const float* l0_eb = (const float*)d_in[5];
    const float* l0_w1 = (const float*)d_in[6];
    const float* l0_b1 = (const float*)d_in[7];
    const float* l0_w2 = (const float*)d_in[8];
    const float* l0_b2 = (const float*)d_in[9];
    const float* ew    = (const float*)d_in[10];
    const float* eb    = (const float*)d_in[11];
    const float* w1    = (const float*)d_in[12];
    const float* b1    = (const float*)d_in[13];
    const float* w2    = (const float*)d_in[14];
    const float* b2    = (const float*)d_in[15];
    const float* gam   = (const float*)d_in[16];
    const float* bet   = (const float*)d_in[17];
    const float* hw1   = (const float*)d_in[18];
    const float* hb1   = (const float*)d_in[19];
    const float* hw2   = (const float*)d_in[20];
    const float* hb2   = (const float*)d_in[21];
    float* out = (float*)d_out;

    float *hp, *aggp, *statsp, *scp, *sfp, *poolp, *cntp;
    int *curp;
    __half *projA, *projB, *ewhp;
    cudaGetSymbolAddress((void**)&hp, g_h);
    cudaGetSymbolAddress((void**)&aggp, g_agg);
    cudaGetSymbolAddress((void**)&projA, g_projA);
    cudaGetSymbolAddress((void**)&projB, g_projB);
    cudaGetSymbolAddress((void**)&ewhp, g_ewh);
    cudaGetSymbolAddress((void**)&statsp, g_stats);
    cudaGetSymbolAddress((void**)&scp, g_bnsc);
    cudaGetSymbolAddress((void**)&sfp, g_bnsf);
    cudaGetSymbolAddress((void**)&poolp, g_pool);
    cudaGetSymbolAddress((void**)&cntp, g_cnt);
    cudaGetSymbolAddress((void**)&curp, g_cur);

    // side stream + events: created once on the (uncaptured) correctness call,
    // reused identically on every call -> identical captured graph.
    static cudaStream_t side = nullptr;
    static cudaEvent_t evFork, evP0, evP1, evP2, evP3, evA0, evA1;
    if (!side) {
        cudaStreamCreateWithFlags(&side, cudaStreamNonBlocking);
        cudaEventCreateWithFlags(&evFork, cudaEventDisableTiming);
        cudaEventCreateWithFlags(&evP0, cudaEventDisableTiming);
        cudaEventCreateWithFlags(&evP1, cudaEventDisableTiming);
        cudaEventCreateWithFlags(&evP2, cudaEventDisableTiming);
        cudaEventCreateWithFlags(&evP3, cudaEventDisableTiming);
        cudaEventCreateWithFlags(&evA0, cudaEventDisableTiming);
        cudaEventCreateWithFlags(&evA1, cudaEventDisableTiming);
    }

    cudaMemsetAsync(curp, 0, NN * sizeof(int));
    cudaMemsetAsync(statsp, 0, 4 * 2 * HH * sizeof(float));
    cudaMemsetAsync(poolp, 0, GG * HH * sizeof(float));
    cudaMemsetAsync(cntp, 0, GG * sizeof(float));

    hist_kernel<<<(EE + 255) / 256, 256>>>(eidx);
    scan_kernel<<<1, 1024>>>(l0_ew, ew);
    scatter_kernel<<<(EE + 255) / 256, 256>>>(eidx, ea);
    cudaEventRecord(evFork, 0);

    // side chain: eproj layer0 -> A, layer1 -> B (both depend only on scatter)
    cudaStreamWaitEvent(side, evFork, 0);
    eproj_mma_kernel<32><<<EP_BLOCKS, 256, 0, side>>>(ewhp, l0_eb, projA);
    cudaEventRecord(evP0, side);
    eproj_mma_kernel<64><<<EP_BLOCKS, 256, 0, side>>>(ewhp + 512, eb, projB);
    cudaEventRecord(evP1, side);

    // layer 0 (consume A)
    cudaStreamWaitEvent(0, evP0, 0);
    agg32_kernel<<<AGG_BLOCKS, 256>>>(x, projA, aggp);
    cudaEventRecord(evA0, 0);                            // A free after this
    gemm_fused_kernel<32><<<(NN + 63) / 64, 256>>>(aggp, l0_w1, l0_b1, l0_w2, l0_b2, hp, statsp);
    bn_coef_kernel<<<1, 64>>>(statsp, gam, bet, scp, sfp);

    // side: eproj layer2 -> A (after agg32 released A)
    cudaStreamWaitEvent(side, evA0, 0);
    eproj_mma_kernel<64><<<EP_BLOCKS, 256, 0, side>>>(ewhp + 512 + 1024, eb + HH, projA);
    cudaEventRecord(evP2, side);

    // layer 1 (consume B)
    cudaStreamWaitEvent(0, evP1, 0);
    agg64_kernel<<<AGG_BLOCKS, 256>>>(hp, (const __half2*)projB, scp, sfp, aggp);
    cudaEventRecord(evA1, 0);                            // B free after this
    gemm_fused_kernel<64><<<(NN + 63) / 64, 256>>>(aggp, w1, b1, w2, b2, hp, statsp + 2 * HH);
    bn_coef_kernel<<<1, 64>>>(statsp + 2 * HH, gam + HH, bet + HH, scp + HH, sfp + HH);

    // side: eproj layer3 -> B (after agg64_1 released B)
    cudaStreamWaitEvent(side, evA1, 0);
    eproj_mma_kernel<64><<<EP_BLOCKS, 256, 0, side>>>(ewhp + 512 + 2048, eb + 2 * HH, projB);
    cudaEventRecord(evP3, side);

    // layer 2 (consume A)
    cudaStreamWaitEvent(0, evP2, 0);
    agg64_kernel<<<AGG_BLOCKS, 256>>>(hp, (const __half2*)projA, scp + HH, sfp + HH, aggp);
    gemm_fused_kernel<64><<<(NN + 63) / 64, 256>>>(aggp, w1 + HH * HH, b1 + HH,
                                                   w2 + HH * HH, b2 + HH, hp, statsp + 4 * HH);
    bn_coef_kernel<<<1, 64>>>(statsp + 4 * HH, gam + 2 * HH, bet + 2 * HH,
                              scp + 2 * HH, sfp + 2 * HH);

    // layer 3 (consume B)
    cudaStreamWaitEvent(0, evP3, 0);
    agg64_kernel<<<AGG_BLOCKS, 256>>>(hp, (const __half2*)projB, scp + 2 * HH, sfp + 2 * HH, aggp);
    gemm_fused_kernel<64><<<(NN + 63) / 64, 256>>>(aggp, w1 + 2 * HH * HH, b1 + 2 * HH,
                                                   w2 + 2 * HH * HH, b2 + 2 * HH, hp,
                                                   statsp + 6 * HH);
    bn_coef_kernel<<<1, 64>>>(statsp + 6 * HH, gam + 3 * HH, bet + 3 * HH,
                              scp + 3 * HH, sfp + 3 * HH);

    pool_kernel<<<(NN + 255) / 256, 256>>>(hp, batch, scp + 3 * HH, sfp + 3 * HH);
    head_kernel<<<GG, 128>>>(hw1, hb1, hw2, hb2, out);
}